// round 3
// baseline (speedup 1.0000x reference)
#include <cuda_runtime.h>

#define NN 50000
#define NE 400000
#define F1 192      // 64 (u_Y) + 128 (X)
#define HID 512

// ---------------- scratch (device globals; no runtime allocation) ----------
__device__ int   g_indeg[NN];
__device__ float g_dinv[NN];
__device__ int   g_rowptr[NN + 1];
__device__ int   g_fillpos[NN];
__device__ int   g_csrsrc[NE];
__device__ float g_s1[(size_t)NN * F1];    // dinv[v] * latent[v]
__device__ float g_agg1[(size_t)NN * F1];  // aggregated layer-1 input
__device__ float g_z2[NN * 2];             // h1 @ W2 (accumulated by GEMM epilogue)

// ---------------- init: zero indeg and z2 ----------------------------------
__global__ void k_init() {
    int i = blockIdx.x * blockDim.x + threadIdx.x;
    if (i < NN) g_indeg[i] = 0;
    if (i < NN * 2) g_z2[i] = 0.f;
}

// ---------------- in-degree histogram over targets --------------------------
__global__ void k_degree(const int* __restrict__ col) {
    int e = blockIdx.x * blockDim.x + threadIdx.x;
    if (e < NE) atomicAdd(&g_indeg[col[e]], 1);
}

// ---------------- dinv = rsqrt(deg) with self-loop ---------------------------
__global__ void k_dinv() {
    int v = blockIdx.x * blockDim.x + threadIdx.x;
    if (v < NN) g_dinv[v] = rsqrtf((float)g_indeg[v] + 1.0f);
}

// ---------------- exclusive scan of indeg -> rowptr (single block) -----------
__global__ void k_scan() {
    __shared__ int sh[1024];
    __shared__ int carry;
    if (threadIdx.x == 0) carry = 0;
    __syncthreads();
    for (int base = 0; base < NN; base += 1024) {
        int i = base + threadIdx.x;
        int v = (i < NN) ? g_indeg[i] : 0;
        sh[threadIdx.x] = v;
        __syncthreads();
        #pragma unroll
        for (int off = 1; off < 1024; off <<= 1) {
            int t = (threadIdx.x >= off) ? sh[threadIdx.x - off] : 0;
            __syncthreads();
            sh[threadIdx.x] += t;
            __syncthreads();
        }
        int incl = sh[threadIdx.x];
        int excl = carry + incl - v;
        if (i < NN) { g_rowptr[i] = excl; g_fillpos[i] = excl; }
        __syncthreads();
        if (threadIdx.x == 1023) carry += incl;
        __syncthreads();
    }
    if (threadIdx.x == 0) g_rowptr[NN] = carry;   // == NE
}

// ---------------- CSR fill (sources grouped by target) -----------------------
__global__ void k_fill(const int* __restrict__ row, const int* __restrict__ col) {
    int e = blockIdx.x * blockDim.x + threadIdx.x;
    if (e < NE) {
        int p = atomicAdd(&g_fillpos[col[e]], 1);
        g_csrsrc[p] = row[e];
    }
}

// ---------------- s1 = dinv[v] * concat(u_Y, X) ------------------------------
__global__ void k_s1(const float* __restrict__ X, const float* __restrict__ uY) {
    int idx = blockIdx.x * blockDim.x + threadIdx.x;
    if (idx >= NN * F1) return;
    int v = idx / F1, j = idx - v * F1;
    float val = (j < 64) ? uY[v * 64 + j] : X[v * 128 + (j - 64)];
    g_s1[idx] = g_dinv[v] * val;
}

// ---------------- layer-1 aggregation: agg1[v] = dinv[v]*(s1[v]+sum_in s1[u])-
__global__ void k_agg1() {
    int v = blockIdx.x;
    int j = threadIdx.x;
    float acc = g_s1[(size_t)v * F1 + j];
    int beg = g_rowptr[v], end = g_rowptr[v + 1];
    for (int e = beg; e < end; e++) {
        int u = g_csrsrc[e];
        acc += g_s1[(size_t)u * F1 + j];
    }
    g_agg1[(size_t)v * F1 + j] = g_dinv[v] * acc;
}

// ---------------- GEMM: h1 = relu(agg1 @ W1 + b1); z2 += h1 @ W2 (fused) -----
// 64x64 tile, K split in two 96-passes, 256 threads, 4x4 microtile.
__global__ __launch_bounds__(256) void k_gemm(const float* __restrict__ W1,
                                              const float* __restrict__ b1,
                                              const float* __restrict__ W2) {
    __shared__ float As[96][64];   // [k][m]
    __shared__ float Bs[96][64];   // [k][n]
    int tid = threadIdx.x;
    int tx = tid & 15, ty = tid >> 4;
    int rowbase = blockIdx.y * 64;
    int colbase = blockIdx.x * 64;

    float acc[4][4] = {};

    for (int kk = 0; kk < F1; kk += 96) {
        #pragma unroll
        for (int l = 0; l < 6; l++) {
            int idx = l * 256 + tid;
            // A tile: 64 rows x 96 k, float4 along k, transpose into As[k][m]
            int m = idx / 24;
            int kq = idx - m * 24;
            int r = rowbase + m;
            float4 av = make_float4(0.f, 0.f, 0.f, 0.f);
            if (r < NN)
                av = *(const float4*)(&g_agg1[(size_t)r * F1 + kk + kq * 4]);
            As[kq * 4 + 0][m] = av.x;
            As[kq * 4 + 1][m] = av.y;
            As[kq * 4 + 2][m] = av.z;
            As[kq * 4 + 3][m] = av.w;
            // B tile: 96 k x 64 n, coalesced float4 along n
            int k = idx / 16;
            int n4 = idx - k * 16;
            *(float4*)&Bs[k][n4 * 4] =
                *(const float4*)(&W1[(size_t)(kk + k) * HID + colbase + n4 * 4]);
        }
        __syncthreads();
        #pragma unroll 8
        for (int k = 0; k < 96; k++) {
            float4 a = *(float4*)&As[k][ty * 4];
            float4 b = *(float4*)&Bs[k][tx * 4];
            acc[0][0] += a.x * b.x; acc[0][1] += a.x * b.y; acc[0][2] += a.x * b.z; acc[0][3] += a.x * b.w;
            acc[1][0] += a.y * b.x; acc[1][1] += a.y * b.y; acc[1][2] += a.y * b.z; acc[1][3] += a.y * b.w;
            acc[2][0] += a.z * b.x; acc[2][1] += a.z * b.y; acc[2][2] += a.z * b.z; acc[2][3] += a.z * b.w;
            acc[3][0] += a.w * b.x; acc[3][1] += a.w * b.y; acc[3][2] += a.w * b.z; acc[3][3] += a.w * b.w;
        }
        __syncthreads();
    }

    // Epilogue: bias + ReLU, then partial h1 @ W2 (2 outputs), never store h1.
    float p[4][2] = {};
    #pragma unroll
    for (int i = 0; i < 4; i++) {
        #pragma unroll
        for (int j = 0; j < 4; j++) {
            int c = colbase + tx * 4 + j;
            float v = acc[i][j] + __ldg(&b1[c]);
            v = fmaxf(v, 0.f);
            p[i][0] += v * __ldg(&W2[c * 2 + 0]);
            p[i][1] += v * __ldg(&W2[c * 2 + 1]);
        }
    }
    // reduce over tx within each 16-lane half-warp
    #pragma unroll
    for (int off = 8; off >= 1; off >>= 1) {
        #pragma unroll
        for (int i = 0; i < 4; i++) {
            p[i][0] += __shfl_xor_sync(0xffffffffu, p[i][0], off);
            p[i][1] += __shfl_xor_sync(0xffffffffu, p[i][1], off);
        }
    }
    if (tx == 0) {
        #pragma unroll
        for (int i = 0; i < 4; i++) {
            int r = rowbase + ty * 4 + i;
            if (r < NN) {
                atomicAdd(&g_z2[r * 2 + 0], p[i][0]);
                atomicAdd(&g_z2[r * 2 + 1], p[i][1]);
            }
        }
    }
}

// ---------------- layer-2 aggregation + bias + softmax -----------------------
__global__ void k_final(const float* __restrict__ b2, float* __restrict__ out) {
    int v = blockIdx.x * blockDim.x + threadIdx.x;
    if (v >= NN) return;
    float dv = g_dinv[v];
    float s0 = dv * g_z2[v * 2 + 0];
    float s1v = dv * g_z2[v * 2 + 1];
    int beg = g_rowptr[v], end = g_rowptr[v + 1];
    for (int e = beg; e < end; e++) {
        int u = g_csrsrc[e];
        float du = g_dinv[u];
        s0 += du * g_z2[u * 2 + 0];
        s1v += du * g_z2[u * 2 + 1];
    }
    float y0 = dv * s0 + b2[0];
    float y1 = dv * s1v + b2[1];
    float m = fmaxf(y0, y1);
    float e0 = __expf(y0 - m), e1 = __expf(y1 - m);
    float inv = 1.f / (e0 + e1);
    out[v * 2 + 0] = e0 * inv;
    out[v * 2 + 1] = e1 * inv;
}

// ---------------- launch ------------------------------------------------------
extern "C" void kernel_launch(void* const* d_in, const int* in_sizes, int n_in,
                              void* d_out, int out_size) {
    const int*   ei = (const int*)d_in[0];
    const float* X  = (const float*)d_in[1];
    const float* uY = (const float*)d_in[2];
    const float* W1 = (const float*)d_in[3];
    const float* b1 = (const float*)d_in[4];
    const float* W2 = (const float*)d_in[5];
    const float* b2 = (const float*)d_in[6];
    float* out = (float*)d_out;
    (void)in_sizes; (void)n_in; (void)out_size;

    const int* row = ei;        // edge_index[0] = sources
    const int* col = ei + NE;   // edge_index[1] = targets

    k_init  <<<(NN * 2 + 255) / 256, 256>>>();
    k_degree<<<(NE + 255) / 256, 256>>>(col);
    k_dinv  <<<(NN + 255) / 256, 256>>>();
    k_scan  <<<1, 1024>>>();
    k_fill  <<<(NE + 255) / 256, 256>>>(row, col);
    k_s1    <<<(NN * F1 + 255) / 256, 256>>>(X, uY);
    k_agg1  <<<NN, F1>>>();
    k_gemm  <<<dim3(HID / 64, (NN + 63) / 64), 256>>>(W1, b1, W2);
    k_final <<<(NN + 255) / 256, 256>>>(b2, out);
}

// round 4
// speedup vs baseline: 1.6918x; 1.6918x over previous
#include <cuda_runtime.h>

#define NN 50000
#define NE 400000
#define F1 192      // 64 (u_Y) + 128 (X)
#define HID 512
#define SCAN_B 256
#define NBLK ((NN + SCAN_B - 1) / SCAN_B)   // 196

// ---------------- scratch (device globals; no runtime allocation) ----------
__device__ int   g_indeg[NN];
__device__ float g_dinv[NN];
__device__ int   g_rowptr[NN + 1];
__device__ int   g_fillpos[NN];
__device__ int   g_csrsrc[NE];
__device__ int   g_part[NBLK];
__device__ float g_s1[(size_t)NN * F1];    // dinv[v] * latent[v]
__device__ float g_agg1[(size_t)NN * F1];  // aggregated layer-1 input
__device__ float g_z2[NN * 2];             // h1 @ W2 (accumulated by GEMM epilogue)

// ---------------- packed f32x2 helpers ---------------------------------------
__device__ __forceinline__ unsigned long long fma2(unsigned long long a,
                                                   unsigned long long b,
                                                   unsigned long long c) {
    unsigned long long d;
    asm("fma.rn.f32x2 %0, %1, %2, %3;" : "=l"(d) : "l"(a), "l"(b), "l"(c));
    return d;
}
__device__ __forceinline__ unsigned long long dup2(float x) {
    unsigned long long d;
    asm("mov.b64 %0, {%1, %1};" : "=l"(d) : "f"(x));
    return d;
}
__device__ __forceinline__ void unpack2(float& lo, float& hi, unsigned long long v) {
    asm("mov.b64 {%0, %1}, %2;" : "=f"(lo), "=f"(hi) : "l"(v));
}

// ---------------- init: zero indeg and z2 ----------------------------------
__global__ void k_init() {
    int i = blockIdx.x * blockDim.x + threadIdx.x;
    if (i < NN) g_indeg[i] = 0;
    if (i < NN * 2) g_z2[i] = 0.f;
}

// ---------------- in-degree histogram over targets --------------------------
__global__ void k_degree(const int* __restrict__ col) {
    int e = blockIdx.x * blockDim.x + threadIdx.x;
    if (e < NE) atomicAdd(&g_indeg[col[e]], 1);
}

// ---------------- dinv = rsqrt(deg) with self-loop ---------------------------
__global__ void k_dinv() {
    int v = blockIdx.x * blockDim.x + threadIdx.x;
    if (v < NN) g_dinv[v] = rsqrtf((float)g_indeg[v] + 1.0f);
}

// ---------------- multi-block exclusive scan of indeg -> rowptr --------------
__global__ void k_scan1() {   // per-block sums
    __shared__ int sh[SCAN_B];
    int t = threadIdx.x;
    int i = blockIdx.x * SCAN_B + t;
    sh[t] = (i < NN) ? g_indeg[i] : 0;
    __syncthreads();
    #pragma unroll
    for (int off = SCAN_B / 2; off >= 1; off >>= 1) {
        if (t < off) sh[t] += sh[t + off];
        __syncthreads();
    }
    if (t == 0) g_part[blockIdx.x] = sh[0];
}
__global__ void k_scan2() {   // single block: exclusive scan of 196 partials
    __shared__ int sh[SCAN_B];
    int t = threadIdx.x;
    int v = (t < NBLK) ? g_part[t] : 0;
    sh[t] = v;
    __syncthreads();
    #pragma unroll
    for (int off = 1; off < SCAN_B; off <<= 1) {
        int x = (t >= off) ? sh[t - off] : 0;
        __syncthreads();
        sh[t] += x;
        __syncthreads();
    }
    if (t < NBLK) g_part[t] = sh[t] - v;   // exclusive
    if (t == 0) g_rowptr[NN] = NE;
}
__global__ void k_scan3() {   // per-block rescan + carry
    __shared__ int sh[SCAN_B];
    int t = threadIdx.x;
    int i = blockIdx.x * SCAN_B + t;
    int v = (i < NN) ? g_indeg[i] : 0;
    sh[t] = v;
    __syncthreads();
    #pragma unroll
    for (int off = 1; off < SCAN_B; off <<= 1) {
        int x = (t >= off) ? sh[t - off] : 0;
        __syncthreads();
        sh[t] += x;
        __syncthreads();
    }
    int excl = sh[t] - v + g_part[blockIdx.x];
    if (i < NN) { g_rowptr[i] = excl; g_fillpos[i] = excl; }
}

// ---------------- CSR fill (sources grouped by target) -----------------------
__global__ void k_fill(const int* __restrict__ row, const int* __restrict__ col) {
    int e = blockIdx.x * blockDim.x + threadIdx.x;
    if (e < NE) {
        int p = atomicAdd(&g_fillpos[col[e]], 1);
        g_csrsrc[p] = row[e];
    }
}

// ---------------- s1 = dinv[v] * concat(u_Y, X) ------------------------------
__global__ void k_s1(const float* __restrict__ X, const float* __restrict__ uY) {
    int idx = blockIdx.x * blockDim.x + threadIdx.x;
    if (idx >= NN * F1) return;
    int v = idx / F1, j = idx - v * F1;
    float val = (j < 64) ? uY[v * 64 + j] : X[v * 128 + (j - 64)];
    g_s1[idx] = g_dinv[v] * val;
}

// ---------------- layer-1 aggregation: agg1[v] = dinv[v]*(s1[v]+sum_in s1[u])-
__global__ void k_agg1() {
    int v = blockIdx.x;
    int j = threadIdx.x;
    float acc = g_s1[(size_t)v * F1 + j];
    int beg = g_rowptr[v], end = g_rowptr[v + 1];
    for (int e = beg; e < end; e++) {
        int u = g_csrsrc[e];
        acc += g_s1[(size_t)u * F1 + j];
    }
    g_agg1[(size_t)v * F1 + j] = g_dinv[v] * acc;
}

// ---------------- GEMM: h1 = relu(agg1 @ W1 + b1); z2 += h1 @ W2 (fused) -----
// 128x128 tile, BK=16, 256 threads, 8x8 microtile, packed fma.rn.f32x2,
// smem double-buffered. K = 192 = 12 k-tiles.
__global__ __launch_bounds__(256, 2) void k_gemm(const float* __restrict__ W1,
                                                 const float* __restrict__ b1,
                                                 const float* __restrict__ W2) {
    __shared__ float As[2][16][128];   // [k][m]
    __shared__ float Bs[2][16][128];   // [k][n]
    int tid = threadIdx.x;
    int tx = tid & 15, ty = tid >> 4;
    int rowbase = blockIdx.y * 128;
    int colbase = blockIdx.x * 128;

    // loader mapping
    int am  = tid & 127;   // A: row within tile
    int ag  = tid >> 7;    // A: float4 k-group (handles ag, ag+2)
    int bn4 = tid & 31;    // B: float4 column
    int bk  = tid >> 5;    // B: k row (handles bk, bk+8)

    float4 aReg[2], bReg[2];

    // --- prefetch tile 0 into registers ---
    #pragma unroll
    for (int t = 0; t < 2; t++) {
        int g = ag + t * 2;
        int r = rowbase + am;
        aReg[t] = (r < NN) ? *(const float4*)(&g_agg1[(size_t)r * F1 + g * 4])
                           : make_float4(0.f, 0.f, 0.f, 0.f);
        int k = bk + t * 8;
        bReg[t] = *(const float4*)(&W1[(size_t)k * HID + colbase + bn4 * 4]);
    }
    // store tile 0
    #pragma unroll
    for (int t = 0; t < 2; t++) {
        int g = ag + t * 2;
        As[0][g * 4 + 0][am] = aReg[t].x;
        As[0][g * 4 + 1][am] = aReg[t].y;
        As[0][g * 4 + 2][am] = aReg[t].z;
        As[0][g * 4 + 3][am] = aReg[t].w;
        *(float4*)&Bs[0][bk + t * 8][bn4 * 4] = bReg[t];
    }
    __syncthreads();

    unsigned long long acc2[8][4];
    #pragma unroll
    for (int i = 0; i < 8; i++)
        #pragma unroll
        for (int j = 0; j < 4; j++) acc2[i][j] = 0ull;   // two packed 0.0f

    #pragma unroll
    for (int it = 0; it < 12; it++) {
        int buf = it & 1;
        // prefetch next tile (registers)
        if (it < 11) {
            int kk = (it + 1) * 16;
            #pragma unroll
            for (int t = 0; t < 2; t++) {
                int g = ag + t * 2;
                int r = rowbase + am;
                aReg[t] = (r < NN)
                    ? *(const float4*)(&g_agg1[(size_t)r * F1 + kk + g * 4])
                    : make_float4(0.f, 0.f, 0.f, 0.f);
                int k = bk + t * 8;
                bReg[t] = *(const float4*)(&W1[(size_t)(kk + k) * HID + colbase + bn4 * 4]);
            }
        }
        // compute on current buffer
        #pragma unroll
        for (int k = 0; k < 16; k++) {
            float4 a0 = *(float4*)&As[buf][k][ty * 8];
            float4 a1 = *(float4*)&As[buf][k][ty * 8 + 4];
            ulonglong2 b0 = *(ulonglong2*)&Bs[buf][k][tx * 8];
            ulonglong2 b1v = *(ulonglong2*)&Bs[buf][k][tx * 8 + 4];
            unsigned long long bp[4] = { b0.x, b0.y, b1v.x, b1v.y };
            unsigned long long ap[8];
            ap[0] = dup2(a0.x); ap[1] = dup2(a0.y); ap[2] = dup2(a0.z); ap[3] = dup2(a0.w);
            ap[4] = dup2(a1.x); ap[5] = dup2(a1.y); ap[6] = dup2(a1.z); ap[7] = dup2(a1.w);
            #pragma unroll
            for (int i = 0; i < 8; i++)
                #pragma unroll
                for (int j = 0; j < 4; j++)
                    acc2[i][j] = fma2(ap[i], bp[j], acc2[i][j]);
        }
        // store next tile into other buffer
        if (it < 11) {
            #pragma unroll
            for (int t = 0; t < 2; t++) {
                int g = ag + t * 2;
                As[buf ^ 1][g * 4 + 0][am] = aReg[t].x;
                As[buf ^ 1][g * 4 + 1][am] = aReg[t].y;
                As[buf ^ 1][g * 4 + 2][am] = aReg[t].z;
                As[buf ^ 1][g * 4 + 3][am] = aReg[t].w;
                *(float4*)&Bs[buf ^ 1][bk + t * 8][bn4 * 4] = bReg[t];
            }
        }
        __syncthreads();
    }

    // Epilogue: bias + ReLU, partial h1 @ W2 (2 outputs), h1 never stored.
    float p0[8] = {}, p1[8] = {};
    #pragma unroll
    for (int i = 0; i < 8; i++) {
        #pragma unroll
        for (int j = 0; j < 4; j++) {
            float lo, hi;
            unpack2(lo, hi, acc2[i][j]);
            int c = colbase + tx * 8 + j * 2;
            float v0 = fmaxf(lo + __ldg(&b1[c]), 0.f);
            float v1 = fmaxf(hi + __ldg(&b1[c + 1]), 0.f);
            p0[i] += v0 * __ldg(&W2[c * 2 + 0]) + v1 * __ldg(&W2[c * 2 + 2]);
            p1[i] += v0 * __ldg(&W2[c * 2 + 1]) + v1 * __ldg(&W2[c * 2 + 3]);
        }
    }
    // reduce across tx (16 lanes; lane = ty*16+tx within warp, xor flips tx bits)
    #pragma unroll
    for (int off = 8; off >= 1; off >>= 1) {
        #pragma unroll
        for (int i = 0; i < 8; i++) {
            p0[i] += __shfl_xor_sync(0xffffffffu, p0[i], off);
            p1[i] += __shfl_xor_sync(0xffffffffu, p1[i], off);
        }
    }
    if (tx == 0) {
        #pragma unroll
        for (int i = 0; i < 8; i++) {
            int r = rowbase + ty * 8 + i;
            if (r < NN) {
                atomicAdd(&g_z2[r * 2 + 0], p0[i]);
                atomicAdd(&g_z2[r * 2 + 1], p1[i]);
            }
        }
    }
}

// ---------------- layer-2 aggregation + bias + softmax -----------------------
__global__ void k_final(const float* __restrict__ b2, float* __restrict__ out) {
    int v = blockIdx.x * blockDim.x + threadIdx.x;
    if (v >= NN) return;
    float dv = g_dinv[v];
    float s0 = dv * g_z2[v * 2 + 0];
    float s1v = dv * g_z2[v * 2 + 1];
    int beg = g_rowptr[v], end = g_rowptr[v + 1];
    for (int e = beg; e < end; e++) {
        int u = g_csrsrc[e];
        float du = g_dinv[u];
        s0 += du * g_z2[u * 2 + 0];
        s1v += du * g_z2[u * 2 + 1];
    }
    float y0 = dv * s0 + b2[0];
    float y1 = dv * s1v + b2[1];
    float m = fmaxf(y0, y1);
    float e0 = __expf(y0 - m), e1 = __expf(y1 - m);
    float inv = 1.f / (e0 + e1);
    out[v * 2 + 0] = e0 * inv;
    out[v * 2 + 1] = e1 * inv;
}

// ---------------- launch ------------------------------------------------------
extern "C" void kernel_launch(void* const* d_in, const int* in_sizes, int n_in,
                              void* d_out, int out_size) {
    const int*   ei = (const int*)d_in[0];
    const float* X  = (const float*)d_in[1];
    const float* uY = (const float*)d_in[2];
    const float* W1 = (const float*)d_in[3];
    const float* b1 = (const float*)d_in[4];
    const float* W2 = (const float*)d_in[5];
    const float* b2 = (const float*)d_in[6];
    float* out = (float*)d_out;
    (void)in_sizes; (void)n_in; (void)out_size;

    const int* row = ei;        // edge_index[0] = sources
    const int* col = ei + NE;   // edge_index[1] = targets

    k_init  <<<(NN * 2 + 255) / 256, 256>>>();
    k_degree<<<(NE + 255) / 256, 256>>>(col);
    k_dinv  <<<(NN + 255) / 256, 256>>>();
    k_scan1 <<<NBLK, SCAN_B>>>();
    k_scan2 <<<1, SCAN_B>>>();
    k_scan3 <<<NBLK, SCAN_B>>>();
    k_fill  <<<(NE + 255) / 256, 256>>>(row, col);
    k_s1    <<<(NN * F1 + 255) / 256, 256>>>(X, uY);
    k_agg1  <<<NN, F1>>>();
    k_gemm  <<<dim3(HID / 128, (NN + 127) / 128), 256>>>(W1, b1, W2);
    k_final <<<(NN + 255) / 256, 256>>>(b2, out);
}

// round 10
// speedup vs baseline: 2.6475x; 1.5649x over previous
#include <cuda_runtime.h>
#include <cuda_bf16.h>
#include <cstdint>

#define NN 50000
#define NE 400000
#define F1 192      // 64 (u_Y) + 128 (X)
#define HID 512
#define SCAN_B 256
#define NBLK ((NN + SCAN_B - 1) / SCAN_B)   // 196

// GEMM tiling (mma.sync path — baseline PTX; static 48KB smem, no attribute call)
#define TM 128
#define TN 64
#define KC 64                       // K-chunk: 64 bf16 = 128 B row (SW128)
#define NCHUNK (F1 / KC)            // 3

// ---------------- scratch (device globals; no runtime allocation) ----------
__device__ int   g_indeg[NN];
__device__ float g_dinv[NN];
__device__ int   g_rowptr[NN + 1];
__device__ int   g_fillpos[NN];
__device__ int   g_csrsrc[NE];
__device__ int   g_part[NBLK];
__device__ float g_s1[(size_t)NN * F1];          // dinv[v] * latent[v]
__device__ __nv_bfloat16 g_Ah[(size_t)NN * F1];  // bf16 hi of aggregated input
__device__ __nv_bfloat16 g_Al[(size_t)NN * F1];  // bf16 lo residual
__device__ __nv_bfloat16 g_Bh[(size_t)HID * F1]; // W1^T hi  [n][k]
__device__ __nv_bfloat16 g_Bl[(size_t)HID * F1]; // W1^T lo
__device__ float g_z2[NN * 2];                   // h1 @ W2 partials

// ---------------- PTX helpers (baseline ISA only) ---------------------------
__device__ __forceinline__ uint32_t smem_u32(const void* p) {
    return (uint32_t)__cvta_generic_to_shared(p);
}
__device__ __forceinline__ uint32_t sw128(uint32_t off) {
    return off ^ ((off >> 3) & 0x70);
}
__device__ __forceinline__ void ldm_x4(uint32_t* r, uint32_t addr) {
    asm volatile("ldmatrix.sync.aligned.m8n8.x4.shared.b16 {%0,%1,%2,%3}, [%4];"
                 : "=r"(r[0]), "=r"(r[1]), "=r"(r[2]), "=r"(r[3]) : "r"(addr));
}
__device__ __forceinline__ void mma16816(float* d, const uint32_t* a, const uint32_t* b) {
    asm volatile(
        "mma.sync.aligned.m16n8k16.row.col.f32.bf16.bf16.f32 "
        "{%0,%1,%2,%3}, {%4,%5,%6,%7}, {%8,%9}, {%0,%1,%2,%3};"
        : "+f"(d[0]), "+f"(d[1]), "+f"(d[2]), "+f"(d[3])
        : "r"(a[0]), "r"(a[1]), "r"(a[2]), "r"(a[3]), "r"(b[0]), "r"(b[1]));
}

// ---------------- init: zero indeg and z2 ----------------------------------
__global__ void k_init() {
    int i = blockIdx.x * blockDim.x + threadIdx.x;
    if (i < NN) g_indeg[i] = 0;
    if (i < NN * 2) g_z2[i] = 0.f;
}

// ---------------- in-degree histogram over targets --------------------------
__global__ void k_degree(const int* __restrict__ col) {
    int e = blockIdx.x * blockDim.x + threadIdx.x;
    if (e < NE) atomicAdd(&g_indeg[col[e]], 1);
}

// ---------------- dinv = rsqrt(deg) with self-loop ---------------------------
__global__ void k_dinv() {
    int v = blockIdx.x * blockDim.x + threadIdx.x;
    if (v < NN) g_dinv[v] = rsqrtf((float)g_indeg[v] + 1.0f);
}

// ---------------- multi-block exclusive scan of indeg -> rowptr --------------
__global__ void k_scan1() {
    __shared__ int sh[SCAN_B];
    int t = threadIdx.x;
    int i = blockIdx.x * SCAN_B + t;
    sh[t] = (i < NN) ? g_indeg[i] : 0;
    __syncthreads();
    #pragma unroll
    for (int off = SCAN_B / 2; off >= 1; off >>= 1) {
        if (t < off) sh[t] += sh[t + off];
        __syncthreads();
    }
    if (t == 0) g_part[blockIdx.x] = sh[0];
}
__global__ void k_scan2() {
    __shared__ int sh[SCAN_B];
    int t = threadIdx.x;
    int v = (t < NBLK) ? g_part[t] : 0;
    sh[t] = v;
    __syncthreads();
    #pragma unroll
    for (int off = 1; off < SCAN_B; off <<= 1) {
        int x = (t >= off) ? sh[t - off] : 0;
        __syncthreads();
        sh[t] += x;
        __syncthreads();
    }
    if (t < NBLK) g_part[t] = sh[t] - v;
    if (t == 0) g_rowptr[NN] = NE;
}
__global__ void k_scan3() {
    __shared__ int sh[SCAN_B];
    int t = threadIdx.x;
    int i = blockIdx.x * SCAN_B + t;
    int v = (i < NN) ? g_indeg[i] : 0;
    sh[t] = v;
    __syncthreads();
    #pragma unroll
    for (int off = 1; off < SCAN_B; off <<= 1) {
        int x = (t >= off) ? sh[t - off] : 0;
        __syncthreads();
        sh[t] += x;
        __syncthreads();
    }
    int excl = sh[t] - v + g_part[blockIdx.x];
    if (i < NN) { g_rowptr[i] = excl; g_fillpos[i] = excl; }
}

// ---------------- CSR fill ---------------------------------------------------
__global__ void k_fill(const int* __restrict__ row, const int* __restrict__ col) {
    int e = blockIdx.x * blockDim.x + threadIdx.x;
    if (e < NE) {
        int p = atomicAdd(&g_fillpos[col[e]], 1);
        g_csrsrc[p] = row[e];
    }
}

// ---------------- s1 = dinv[v] * concat(u_Y, X) ------------------------------
__global__ void k_s1(const float* __restrict__ X, const float* __restrict__ uY) {
    int idx = blockIdx.x * blockDim.x + threadIdx.x;
    if (idx >= NN * F1) return;
    int v = idx / F1, j = idx - v * F1;
    float val = (j < 64) ? uY[v * 64 + j] : X[v * 128 + (j - 64)];
    g_s1[idx] = g_dinv[v] * val;
}

// ---------------- layer-1 aggregation + bf16 hi/lo split ---------------------
__global__ void k_agg1() {
    int v = blockIdx.x;
    int j = threadIdx.x;
    float acc = g_s1[(size_t)v * F1 + j];
    int beg = g_rowptr[v], end = g_rowptr[v + 1];
    for (int e = beg; e < end; e++) {
        int u = g_csrsrc[e];
        acc += g_s1[(size_t)u * F1 + j];
    }
    float val = g_dinv[v] * acc;
    __nv_bfloat16 h = __float2bfloat16(val);
    g_Ah[(size_t)v * F1 + j] = h;
    g_Al[(size_t)v * F1 + j] = __float2bfloat16(val - __bfloat162float(h));
}

// ---------------- W1 transpose + bf16 split: g_B*[n][k] = split(W1[k][n]) ----
__global__ void k_splitB(const float* __restrict__ W1) {
    int idx = blockIdx.x * blockDim.x + threadIdx.x;
    if (idx >= HID * F1) return;
    int n = idx / F1, k = idx - n * F1;
    float v = W1[(size_t)k * HID + n];
    __nv_bfloat16 h = __float2bfloat16(v);
    g_Bh[idx] = h;
    g_Bl[idx] = __float2bfloat16(v - __bfloat162float(h));
}

// ---------------- mma.sync GEMM: D = Ah@Bh + Ah@Bl + Al@Bh (fp32 acc) --------
// CTA 128x64; 8 warps (4x2) of 32x32 warp tiles; m16n8k16 bf16 HMMA.
// Static 48KB smem (16+16+8+8). Epilogue folds bias+ReLU+W2 -> g_z2 atomics.
__global__ __launch_bounds__(256) void k_gemm(const float* __restrict__ b1,
                                              const float* __restrict__ W2) {
    __shared__ __nv_bfloat16 sAh[TM * KC];   // 16 KB, 128B rows
    __shared__ __nv_bfloat16 sAl[TM * KC];   // 16 KB
    __shared__ __nv_bfloat16 sBh[TN * KC];   //  8 KB
    __shared__ __nv_bfloat16 sBl[TN * KC];   //  8 KB
    uint32_t bAh = smem_u32(sAh), bAl = smem_u32(sAl);
    uint32_t bBh = smem_u32(sBh), bBl = smem_u32(sBl);

    int tid = threadIdx.x;
    int wid = tid >> 5, lane = tid & 31;
    int wr = wid >> 1;          // 0..3  (32-row band)
    int wc = wid & 1;           // 0..1  (32-col band)
    int rowbase = blockIdx.y * TM;
    int colbase = blockIdx.x * TN;

    float acc[2][4][4];
    #pragma unroll
    for (int i = 0; i < 2; i++)
        #pragma unroll
        for (int j = 0; j < 4; j++)
            #pragma unroll
            for (int c = 0; c < 4; c++) acc[i][j][c] = 0.f;

    // per-lane ldmatrix address components
    int a_row = wr * 32 + (lane & 15);                      // + mt*16
    int a_kb  = (lane & 16);                                // + s*32
    int b_row = wc * 32 + (lane & 7) + ((lane & 16) >> 1);  // + p*16
    int b_kb  = (lane & 8) * 2;                             // + s*32

    for (int c = 0; c < NCHUNK; c++) {
        // ---- cooperative tile load (single buffer) ----
        #pragma unroll
        for (int l = 0; l < 4; l++) {           // A: 128 rows x 8 uint4
            int i = l * 256 + tid;
            int m = i >> 3, k8 = i & 7;
            int r = rowbase + m;
            uint4 vh = make_uint4(0u, 0u, 0u, 0u), vl = vh;
            if (r < NN) {
                size_t g = (size_t)r * F1 + c * KC + k8 * 8;
                vh = *(const uint4*)(&g_Ah[g]);
                vl = *(const uint4*)(&g_Al[g]);
            }
            uint32_t sw = sw128((uint32_t)(m * 128 + k8 * 16));
            *(uint4*)((char*)sAh + sw) = vh;
            *(uint4*)((char*)sAl + sw) = vl;
        }
        #pragma unroll
        for (int l = 0; l < 2; l++) {           // B: 64 rows x 8 uint4
            int i = l * 256 + tid;
            int n = i >> 3, k8 = i & 7;
            size_t g = (size_t)(colbase + n) * F1 + c * KC + k8 * 8;
            uint32_t sw = sw128((uint32_t)(n * 128 + k8 * 16));
            *(uint4*)((char*)sBh + sw) = *(const uint4*)(&g_Bh[g]);
            *(uint4*)((char*)sBl + sw) = *(const uint4*)(&g_Bl[g]);
        }
        __syncthreads();

        // ---- compute: 4 k16-steps x 3 split terms ----
        #pragma unroll
        for (int s = 0; s < 4; s++) {
            uint32_t af[2][4], bh[2][4], bl[2][4];
            #pragma unroll
            for (int p = 0; p < 2; p++) {
                uint32_t off = sw128((uint32_t)((b_row + p * 16) * 128 + s * 32 + b_kb));
                ldm_x4(bh[p], bBh + off);
                ldm_x4(bl[p], bBl + off);
            }
            #pragma unroll
            for (int mt = 0; mt < 2; mt++) {
                uint32_t off = sw128((uint32_t)((a_row + mt * 16) * 128 + s * 32 + a_kb));
                ldm_x4(af[mt], bAh + off);
            }
            // term 1: Ah @ Bh ; term 2: Ah @ Bl
            #pragma unroll
            for (int mt = 0; mt < 2; mt++)
                #pragma unroll
                for (int nt = 0; nt < 4; nt++) {
                    mma16816(acc[mt][nt], af[mt], &bh[nt >> 1][(nt & 1) * 2]);
                    mma16816(acc[mt][nt], af[mt], &bl[nt >> 1][(nt & 1) * 2]);
                }
            // A lo fragments (reuse registers)
            #pragma unroll
            for (int mt = 0; mt < 2; mt++) {
                uint32_t off = sw128((uint32_t)((a_row + mt * 16) * 128 + s * 32 + a_kb));
                ldm_x4(af[mt], bAl + off);
            }
            // term 3: Al @ Bh
            #pragma unroll
            for (int mt = 0; mt < 2; mt++)
                #pragma unroll
                for (int nt = 0; nt < 4; nt++)
                    mma16816(acc[mt][nt], af[mt], &bh[nt >> 1][(nt & 1) * 2]);
        }
        __syncthreads();
    }

    // ---- epilogue: bias + ReLU + W2 fold, straight from registers ----
    // acc[mt][nt][cc]: row = rowbase + wr*32 + mt*16 + (lane>>2) + 8*(cc>>1)
    //                  col = colbase + wc*32 + nt*8 + (lane&3)*2 + (cc&1)
    #pragma unroll
    for (int mt = 0; mt < 2; mt++) {
        #pragma unroll
        for (int rg = 0; rg < 2; rg++) {
            int r = rowbase + wr * 32 + mt * 16 + (lane >> 2) + rg * 8;
            float p0 = 0.f, p1 = 0.f;
            #pragma unroll
            for (int nt = 0; nt < 4; nt++) {
                #pragma unroll
                for (int q = 0; q < 2; q++) {
                    int col = colbase + wc * 32 + nt * 8 + (lane & 3) * 2 + q;
                    float v = fmaxf(acc[mt][nt][rg * 2 + q] + __ldg(&b1[col]), 0.f);
                    p0 += v * __ldg(&W2[col * 2 + 0]);
                    p1 += v * __ldg(&W2[col * 2 + 1]);
                }
            }
            // reduce across the 4 lanes sharing this row (xor bits 0,1)
            p0 += __shfl_xor_sync(0xffffffffu, p0, 1);
            p1 += __shfl_xor_sync(0xffffffffu, p1, 1);
            p0 += __shfl_xor_sync(0xffffffffu, p0, 2);
            p1 += __shfl_xor_sync(0xffffffffu, p1, 2);
            if ((lane & 3) == 0 && r < NN) {
                atomicAdd(&g_z2[r * 2 + 0], p0);
                atomicAdd(&g_z2[r * 2 + 1], p1);
            }
        }
    }
}

// ---------------- layer-2 aggregation + bias + softmax -----------------------
__global__ void k_final(const float* __restrict__ b2, float* __restrict__ out) {
    int v = blockIdx.x * blockDim.x + threadIdx.x;
    if (v >= NN) return;
    float dv = g_dinv[v];
    float s0 = dv * g_z2[v * 2 + 0];
    float s1v = dv * g_z2[v * 2 + 1];
    int beg = g_rowptr[v], end = g_rowptr[v + 1];
    for (int e = beg; e < end; e++) {
        int u = g_csrsrc[e];
        float du = g_dinv[u];
        s0 += du * g_z2[u * 2 + 0];
        s1v += du * g_z2[u * 2 + 1];
    }
    float y0 = dv * s0 + b2[0];
    float y1 = dv * s1v + b2[1];
    float m = fmaxf(y0, y1);
    float e0 = __expf(y0 - m), e1 = __expf(y1 - m);
    float inv = 1.f / (e0 + e1);
    out[v * 2 + 0] = e0 * inv;
    out[v * 2 + 1] = e1 * inv;
}

// ---------------- launch ------------------------------------------------------
extern "C" void kernel_launch(void* const* d_in, const int* in_sizes, int n_in,
                              void* d_out, int out_size) {
    const int*   ei = (const int*)d_in[0];
    const float* X  = (const float*)d_in[1];
    const float* uY = (const float*)d_in[2];
    const float* W1 = (const float*)d_in[3];
    const float* b1 = (const float*)d_in[4];
    const float* W2 = (const float*)d_in[5];
    const float* b2 = (const float*)d_in[6];
    float* out = (float*)d_out;
    (void)in_sizes; (void)n_in; (void)out_size;

    const int* row = ei;        // edge_index[0] = sources
    const int* col = ei + NE;   // edge_index[1] = targets

    k_init  <<<(NN * 2 + 255) / 256, 256>>>();
    k_degree<<<(NE + 255) / 256, 256>>>(col);
    k_splitB<<<(HID * F1 + 255) / 256, 256>>>(W1);
    k_dinv  <<<(NN + 255) / 256, 256>>>();
    k_scan1 <<<NBLK, SCAN_B>>>();
    k_scan2 <<<1, SCAN_B>>>();
    k_scan3 <<<NBLK, SCAN_B>>>();
    k_fill  <<<(NE + 255) / 256, 256>>>(row, col);
    k_s1    <<<(NN * F1 + 255) / 256, 256>>>(X, uY);
    k_agg1  <<<NN, F1>>>();
    k_gemm  <<<dim3(HID / TN, (NN + TM - 1) / TM), 256>>>(b1, W2);
    k_final <<<(NN + 255) / 256, 256>>>(b2, out);
}

// round 12
// speedup vs baseline: 3.3041x; 1.2480x over previous
#include <cuda_runtime.h>
#include <cuda_bf16.h>
#include <cstdint>

#define NN 50000
#define NE 400000
#define F1 192      // 64 (u_Y) + 128 (X)
#define HID 512
#define SCAN_B 256
#define NBLK ((NN + SCAN_B - 1) / SCAN_B)   // 196

// GEMM tiling (mma.sync, baseline PTX; static 32KB smem)
#define TM 128
#define TN 128
#define KC 32                       // K-chunk: 32 bf16 = 64 B row (SW64)
#define NCHUNK (F1 / KC)            // 6

// ---------------- scratch (device globals; no runtime allocation) ----------
__device__ int   g_indeg[NN];
__device__ float g_dinv[NN];
__device__ int   g_rowptr[NN + 1];
__device__ int   g_fillpos[NN];
__device__ int   g_csrsrc[NE];
__device__ int   g_part[NBLK];
__device__ __nv_bfloat16 g_Ah[(size_t)NN * F1];  // bf16 hi of aggregated input
__device__ __nv_bfloat16 g_Al[(size_t)NN * F1];  // bf16 lo residual
__device__ __nv_bfloat16 g_Bh[(size_t)HID * F1]; // W1^T hi  [n][k]
__device__ __nv_bfloat16 g_Bl[(size_t)HID * F1]; // W1^T lo
__device__ float g_z2[NN * 2];                   // h1 @ W2 partials

// ---------------- PTX helpers (baseline ISA only) ---------------------------
__device__ __forceinline__ uint32_t smem_u32(const void* p) {
    return (uint32_t)__cvta_generic_to_shared(p);
}
__device__ __forceinline__ uint32_t sw64(uint32_t off) {
    return off ^ ((off >> 3) & 0x30);
}
__device__ __forceinline__ void ldm_x4(uint32_t* r, uint32_t addr) {
    asm volatile("ldmatrix.sync.aligned.m8n8.x4.shared.b16 {%0,%1,%2,%3}, [%4];"
                 : "=r"(r[0]), "=r"(r[1]), "=r"(r[2]), "=r"(r[3]) : "r"(addr));
}
__device__ __forceinline__ void mma16816(float* d, const uint32_t* a, const uint32_t* b) {
    asm volatile(
        "mma.sync.aligned.m16n8k16.row.col.f32.bf16.bf16.f32 "
        "{%0,%1,%2,%3}, {%4,%5,%6,%7}, {%8,%9}, {%0,%1,%2,%3};"
        : "+f"(d[0]), "+f"(d[1]), "+f"(d[2]), "+f"(d[3])
        : "r"(a[0]), "r"(a[1]), "r"(a[2]), "r"(a[3]), "r"(b[0]), "r"(b[1]));
}

// ---------------- prolog: zero indeg+z2, transpose+split W1 -----------------
#define PROLOG_N (NN * 2 + HID * F1)
__global__ void k_prolog(const float* __restrict__ W1) {
    int i = blockIdx.x * blockDim.x + threadIdx.x;
    if (i < NN * 2) {
        if (i < NN) g_indeg[i] = 0;
        g_z2[i] = 0.f;
    } else if (i < PROLOG_N) {
        int idx = i - NN * 2;
        int n = idx / F1, k = idx - n * F1;
        float v = W1[(size_t)k * HID + n];
        __nv_bfloat16 h = __float2bfloat16(v);
        g_Bh[idx] = h;
        g_Bl[idx] = __float2bfloat16(v - __bfloat162float(h));
    }
}

// ---------------- in-degree histogram over targets --------------------------
__global__ void k_degree(const int* __restrict__ col) {
    int e = blockIdx.x * blockDim.x + threadIdx.x;
    if (e < NE) atomicAdd(&g_indeg[col[e]], 1);
}

// ---------------- scan pass 1 (block sums) + dinv ----------------------------
__global__ void k_scan1() {
    __shared__ int sh[SCAN_B];
    int t = threadIdx.x;
    int i = blockIdx.x * SCAN_B + t;
    int v = (i < NN) ? g_indeg[i] : 0;
    if (i < NN) g_dinv[i] = rsqrtf((float)v + 1.0f);
    sh[t] = v;
    __syncthreads();
    #pragma unroll
    for (int off = SCAN_B / 2; off >= 1; off >>= 1) {
        if (t < off) sh[t] += sh[t + off];
        __syncthreads();
    }
    if (t == 0) g_part[blockIdx.x] = sh[0];
}
__global__ void k_scan2() {
    __shared__ int sh[SCAN_B];
    int t = threadIdx.x;
    int v = (t < NBLK) ? g_part[t] : 0;
    sh[t] = v;
    __syncthreads();
    #pragma unroll
    for (int off = 1; off < SCAN_B; off <<= 1) {
        int x = (t >= off) ? sh[t - off] : 0;
        __syncthreads();
        sh[t] += x;
        __syncthreads();
    }
    if (t < NBLK) g_part[t] = sh[t] - v;
    if (t == 0) g_rowptr[NN] = NE;
}
__global__ void k_scan3() {
    __shared__ int sh[SCAN_B];
    int t = threadIdx.x;
    int i = blockIdx.x * SCAN_B + t;
    int v = (i < NN) ? g_indeg[i] : 0;
    sh[t] = v;
    __syncthreads();
    #pragma unroll
    for (int off = 1; off < SCAN_B; off <<= 1) {
        int x = (t >= off) ? sh[t - off] : 0;
        __syncthreads();
        sh[t] += x;
        __syncthreads();
    }
    int excl = sh[t] - v + g_part[blockIdx.x];
    if (i < NN) { g_rowptr[i] = excl; g_fillpos[i] = excl; }
}

// ---------------- CSR fill ---------------------------------------------------
__global__ void k_fill(const int* __restrict__ row, const int* __restrict__ col) {
    int e = blockIdx.x * blockDim.x + threadIdx.x;
    if (e < NE) {
        int p = atomicAdd(&g_fillpos[col[e]], 1);
        g_csrsrc[p] = row[e];
    }
}

// ---------------- layer-1 aggregation (gathers X/uY directly) + bf16 split ---
__global__ void k_agg1(const float* __restrict__ X, const float* __restrict__ uY) {
    int v = blockIdx.x;
    int j = threadIdx.x;
    float dv = g_dinv[v];
    float self = (j < 64) ? uY[v * 64 + j] : X[v * 128 + (j - 64)];
    float acc = dv * self;
    int beg = g_rowptr[v], end = g_rowptr[v + 1];
    for (int e = beg; e < end; e++) {
        int u = g_csrsrc[e];
        float du = g_dinv[u];
        float val = (j < 64) ? uY[u * 64 + j] : X[u * 128 + (j - 64)];
        acc += du * val;
    }
    float out = dv * acc;
    __nv_bfloat16 h = __float2bfloat16(out);
    g_Ah[(size_t)v * F1 + j] = h;
    g_Al[(size_t)v * F1 + j] = __float2bfloat16(out - __bfloat162float(h));
}

// ---------------- mma.sync GEMM: D = Ah@Bh + Ah@Bl + Al@Bh (fp32 acc) --------
// CTA 128x128; 8 warps in 4x2 grid of 32x64 warp tiles; m16n8k16 bf16 HMMA.
// KC=32 chunks (64B rows, SW64). Static 32KB smem (8+8+8+8).
// Row coverage check: wr in 0..3 covers 4*32=128 rows; wc in 0..1 covers
// 2*64=128 cols; acc[2][8][4] = 64 floats = full 32x64 warp tile. (R11 bug
// was 64-row bands with only 32 rows computed.)
__global__ __launch_bounds__(256) void k_gemm(const float* __restrict__ b1,
                                              const float* __restrict__ W2) {
    __shared__ __nv_bfloat16 sAh[TM * KC];   //  8 KB, 64B rows
    __shared__ __nv_bfloat16 sAl[TM * KC];   //  8 KB
    __shared__ __nv_bfloat16 sBh[TN * KC];   //  8 KB
    __shared__ __nv_bfloat16 sBl[TN * KC];   //  8 KB
    uint32_t bAh = smem_u32(sAh), bAl = smem_u32(sAl);
    uint32_t bBh = smem_u32(sBh), bBl = smem_u32(sBl);

    int tid = threadIdx.x;
    int wid = tid >> 5, lane = tid & 31;
    int wr = wid >> 1;          // 0..3  (32-row band)
    int wc = wid & 1;           // 0..1  (64-col band)
    int rowbase = blockIdx.y * TM;
    int colbase = blockIdx.x * TN;

    float acc[2][8][4];
    #pragma unroll
    for (int i = 0; i < 2; i++)
        #pragma unroll
        for (int j = 0; j < 8; j++)
            #pragma unroll
            for (int c = 0; c < 4; c++) acc[i][j][c] = 0.f;

    // per-lane ldmatrix address components (64B rows)
    int a_row = wr * 32 + (lane & 15);                      // + mt*16
    int a_kb  = (lane & 16);                                // + s*32 byte offset
    int b_row = wc * 64 + (lane & 7) + ((lane & 16) >> 1);  // + p*16
    int b_kb  = (lane & 8) * 2;                             // + s*32

    for (int c = 0; c < NCHUNK; c++) {
        // ---- cooperative tile load ----
        #pragma unroll
        for (int l = 0; l < 2; l++) {           // A: 128 rows x 4 uint4 = 512
            int i = l * 256 + tid;
            int m = i >> 2, g = i & 3;
            int r = rowbase + m;
            uint4 vh = make_uint4(0u, 0u, 0u, 0u), vl = vh;
            if (r < NN) {
                size_t gg = (size_t)r * F1 + c * KC + g * 8;
                vh = *(const uint4*)(&g_Ah[gg]);
                vl = *(const uint4*)(&g_Al[gg]);
            }
            uint32_t sw = sw64((uint32_t)(m * 64 + g * 16));
            *(uint4*)((char*)sAh + sw) = vh;
            *(uint4*)((char*)sAl + sw) = vl;
        }
        #pragma unroll
        for (int l = 0; l < 2; l++) {           // B: 128 rows x 4 uint4 = 512
            int i = l * 256 + tid;
            int n = i >> 2, g = i & 3;
            size_t gg = (size_t)(colbase + n) * F1 + c * KC + g * 8;
            uint32_t sw = sw64((uint32_t)(n * 64 + g * 16));
            *(uint4*)((char*)sBh + sw) = *(const uint4*)(&g_Bh[gg]);
            *(uint4*)((char*)sBl + sw) = *(const uint4*)(&g_Bl[gg]);
        }
        __syncthreads();

        // ---- compute: 2 k16-steps x 3 split terms ----
        #pragma unroll
        for (int s = 0; s < 2; s++) {
            uint32_t af[2][4], bh[4][4], bl[4][4];
            #pragma unroll
            for (int p = 0; p < 4; p++) {
                uint32_t off = sw64((uint32_t)((b_row + p * 16) * 64 + s * 32 + b_kb));
                ldm_x4(bh[p], bBh + off);
                ldm_x4(bl[p], bBl + off);
            }
            #pragma unroll
            for (int mt = 0; mt < 2; mt++) {
                uint32_t off = sw64((uint32_t)((a_row + mt * 16) * 64 + s * 32 + a_kb));
                ldm_x4(af[mt], bAh + off);
            }
            // term 1: Ah @ Bh ; term 2: Ah @ Bl
            #pragma unroll
            for (int mt = 0; mt < 2; mt++)
                #pragma unroll
                for (int nt = 0; nt < 8; nt++) {
                    mma16816(acc[mt][nt], af[mt], &bh[nt >> 1][(nt & 1) * 2]);
                    mma16816(acc[mt][nt], af[mt], &bl[nt >> 1][(nt & 1) * 2]);
                }
            // A lo fragments (reuse registers)
            #pragma unroll
            for (int mt = 0; mt < 2; mt++) {
                uint32_t off = sw64((uint32_t)((a_row + mt * 16) * 64 + s * 32 + a_kb));
                ldm_x4(af[mt], bAl + off);
            }
            // term 3: Al @ Bh
            #pragma unroll
            for (int mt = 0; mt < 2; mt++)
                #pragma unroll
                for (int nt = 0; nt < 8; nt++)
                    mma16816(acc[mt][nt], af[mt], &bh[nt >> 1][(nt & 1) * 2]);
        }
        __syncthreads();
    }

    // ---- epilogue: bias + ReLU + W2 fold, straight from registers ----
    // acc[mt][nt][cc]: row = rowbase + wr*32 + mt*16 + (lane>>2) + 8*(cc>>1)
    //                  col = colbase + wc*64 + nt*8 + (lane&3)*2 + (cc&1)
    #pragma unroll
    for (int mt = 0; mt < 2; mt++) {
        #pragma unroll
        for (int rg = 0; rg < 2; rg++) {
            int r = rowbase + wr * 32 + mt * 16 + (lane >> 2) + rg * 8;
            float p0 = 0.f, p1 = 0.f;
            #pragma unroll
            for (int nt = 0; nt < 8; nt++) {
                #pragma unroll
                for (int q = 0; q < 2; q++) {
                    int col = colbase + wc * 64 + nt * 8 + (lane & 3) * 2 + q;
                    float v = fmaxf(acc[mt][nt][rg * 2 + q] + __ldg(&b1[col]), 0.f);
                    p0 += v * __ldg(&W2[col * 2 + 0]);
                    p1 += v * __ldg(&W2[col * 2 + 1]);
                }
            }
            p0 += __shfl_xor_sync(0xffffffffu, p0, 1);
            p1 += __shfl_xor_sync(0xffffffffu, p1, 1);
            p0 += __shfl_xor_sync(0xffffffffu, p0, 2);
            p1 += __shfl_xor_sync(0xffffffffu, p1, 2);
            if ((lane & 3) == 0 && r < NN) {
                atomicAdd(&g_z2[r * 2 + 0], p0);
                atomicAdd(&g_z2[r * 2 + 1], p1);
            }
        }
    }
}

// ---------------- layer-2 aggregation + bias + softmax -----------------------
__global__ void k_final(const float* __restrict__ b2, float* __restrict__ out) {
    int v = blockIdx.x * blockDim.x + threadIdx.x;
    if (v >= NN) return;
    float dv = g_dinv[v];
    float s0 = dv * g_z2[v * 2 + 0];
    float s1v = dv * g_z2[v * 2 + 1];
    int beg = g_rowptr[v], end = g_rowptr[v + 1];
    for (int e = beg; e < end; e++) {
        int u = g_csrsrc[e];
        float du = g_dinv[u];
        s0 += du * g_z2[u * 2 + 0];
        s1v += du * g_z2[u * 2 + 1];
    }
    float y0 = dv * s0 + b2[0];
    float y1 = dv * s1v + b2[1];
    float m = fmaxf(y0, y1);
    float e0 = __expf(y0 - m), e1 = __expf(y1 - m);
    float inv = 1.f / (e0 + e1);
    out[v * 2 + 0] = e0 * inv;
    out[v * 2 + 1] = e1 * inv;
}

// ---------------- launch ------------------------------------------------------
extern "C" void kernel_launch(void* const* d_in, const int* in_sizes, int n_in,
                              void* d_out, int out_size) {
    const int*   ei = (const int*)d_in[0];
    const float* X  = (const float*)d_in[1];
    const float* uY = (const float*)d_in[2];
    const float* W1 = (const float*)d_in[3];
    const float* b1 = (const float*)d_in[4];
    const float* W2 = (const float*)d_in[5];
    const float* b2 = (const float*)d_in[6];
    float* out = (float*)d_out;
    (void)in_sizes; (void)n_in; (void)out_size;

    const int* row = ei;        // edge_index[0] = sources
    const int* col = ei + NE;   // edge_index[1] = targets

    k_prolog<<<(PROLOG_N + 255) / 256, 256>>>(W1);
    k_degree<<<(NE + 255) / 256, 256>>>(col);
    k_scan1 <<<NBLK, SCAN_B>>>();
    k_scan2 <<<1, SCAN_B>>>();
    k_scan3 <<<NBLK, SCAN_B>>>();
    k_fill  <<<(NE + 255) / 256, 256>>>(row, col);
    k_agg1  <<<NN, F1>>>(X, uY);
    k_gemm  <<<dim3(HID / TN, (NN + TM - 1) / TM), 256>>>(b1, W2);
    k_final <<<(NN + 255) / 256, 256>>>(b2, out);
}

// round 13
// speedup vs baseline: 3.5737x; 1.0816x over previous
#include <cuda_runtime.h>
#include <cuda_bf16.h>
#include <cstdint>

#define NN 50000
#define NE 400000
#define F1 192      // 64 (u_Y) + 128 (X)
#define HID 512
#define SCAN_B 256
#define NBLK ((NN + SCAN_B - 1) / SCAN_B)   // 196

// GEMM tiling (mma.sync + cp.async double buffer; static 32KB smem)
#define TM 128
#define TN 128
#define KC 16                       // K-chunk: 16 bf16 = 32 B row (SW32)
#define NCHUNK (F1 / KC)            // 12

// ---------------- scratch (device globals; no runtime allocation) ----------
__device__ int   g_indeg[NN];
__device__ float g_dinv[NN];
__device__ int   g_rowptr[NN + 1];
__device__ int   g_fillpos[NN];
__device__ int   g_csrsrc[NE];
__device__ int   g_part[NBLK];
__device__ __nv_bfloat16 g_Ah[(size_t)NN * F1];  // bf16 hi of aggregated input
__device__ __nv_bfloat16 g_Al[(size_t)NN * F1];  // bf16 lo residual
__device__ __nv_bfloat16 g_Bh[(size_t)HID * F1]; // W1^T hi  [n][k]
__device__ __nv_bfloat16 g_Bl[(size_t)HID * F1]; // W1^T lo
__device__ float g_z2[NN * 2];                   // h1 @ W2 partials

// ---------------- PTX helpers (baseline ISA only) ---------------------------
__device__ __forceinline__ uint32_t smem_u32(const void* p) {
    return (uint32_t)__cvta_generic_to_shared(p);
}
__device__ __forceinline__ uint32_t sw32(uint32_t off) {
    return off ^ ((off >> 3) & 0x10);
}
__device__ __forceinline__ void ldm_x4(uint32_t* r, uint32_t addr) {
    asm volatile("ldmatrix.sync.aligned.m8n8.x4.shared.b16 {%0,%1,%2,%3}, [%4];"
                 : "=r"(r[0]), "=r"(r[1]), "=r"(r[2]), "=r"(r[3]) : "r"(addr));
}
__device__ __forceinline__ void mma16816(float* d, const uint32_t* a, const uint32_t* b) {
    asm volatile(
        "mma.sync.aligned.m16n8k16.row.col.f32.bf16.bf16.f32 "
        "{%0,%1,%2,%3}, {%4,%5,%6,%7}, {%8,%9}, {%0,%1,%2,%3};"
        : "+f"(d[0]), "+f"(d[1]), "+f"(d[2]), "+f"(d[3])
        : "r"(a[0]), "r"(a[1]), "r"(a[2]), "r"(a[3]), "r"(b[0]), "r"(b[1]));
}
__device__ __forceinline__ void cpa16(uint32_t dst, const void* src, int nbytes) {
    asm volatile("cp.async.cg.shared.global [%0], [%1], 16, %2;"
                 :: "r"(dst), "l"(src), "r"(nbytes));
}
__device__ __forceinline__ void cpa_commit() {
    asm volatile("cp.async.commit_group;" ::: "memory");
}
__device__ __forceinline__ void cpa_wait1() {
    asm volatile("cp.async.wait_group 1;" ::: "memory");
}
__device__ __forceinline__ void cpa_wait0() {
    asm volatile("cp.async.wait_group 0;" ::: "memory");
}

// ---------------- prolog: zero indeg+z2, transpose+split W1 -----------------
#define PROLOG_N (NN * 2 + HID * F1)
__global__ void k_prolog(const float* __restrict__ W1) {
    int i = blockIdx.x * blockDim.x + threadIdx.x;
    if (i < NN * 2) {
        if (i < NN) g_indeg[i] = 0;
        g_z2[i] = 0.f;
    } else if (i < PROLOG_N) {
        int idx = i - NN * 2;
        int n = idx / F1, k = idx - n * F1;
        float v = W1[(size_t)k * HID + n];
        __nv_bfloat16 h = __float2bfloat16(v);
        g_Bh[idx] = h;
        g_Bl[idx] = __float2bfloat16(v - __bfloat162float(h));
    }
}

// ---------------- in-degree histogram over targets --------------------------
__global__ void k_degree(const int* __restrict__ col) {
    int e = blockIdx.x * blockDim.x + threadIdx.x;
    if (e < NE) atomicAdd(&g_indeg[col[e]], 1);
}

// ---------------- scan pass 1 (block sums) + dinv ----------------------------
__global__ void k_scan1() {
    __shared__ int sh[SCAN_B];
    int t = threadIdx.x;
    int i = blockIdx.x * SCAN_B + t;
    int v = (i < NN) ? g_indeg[i] : 0;
    if (i < NN) g_dinv[i] = rsqrtf((float)v + 1.0f);
    sh[t] = v;
    __syncthreads();
    #pragma unroll
    for (int off = SCAN_B / 2; off >= 1; off >>= 1) {
        if (t < off) sh[t] += sh[t + off];
        __syncthreads();
    }
    if (t == 0) g_part[blockIdx.x] = sh[0];
}

// ---------------- scan pass 2: each block re-scans partials + elements -------
__global__ void k_scan3() {
    __shared__ int sh[SCAN_B];
    int t = threadIdx.x;
    int bid = blockIdx.x;
    // inclusive scan of the 196 raw partials (every block does it redundantly)
    int pv = (t < NBLK) ? g_part[t] : 0;
    sh[t] = pv;
    __syncthreads();
    #pragma unroll
    for (int off = 1; off < SCAN_B; off <<= 1) {
        int x = (t >= off) ? sh[t - off] : 0;
        __syncthreads();
        sh[t] += x;
        __syncthreads();
    }
    int prefix = (bid == 0) ? 0 : sh[bid - 1];   // exclusive prefix for this block
    __syncthreads();
    // element scan within this block
    int i = bid * SCAN_B + t;
    int v = (i < NN) ? g_indeg[i] : 0;
    sh[t] = v;
    __syncthreads();
    #pragma unroll
    for (int off = 1; off < SCAN_B; off <<= 1) {
        int x = (t >= off) ? sh[t - off] : 0;
        __syncthreads();
        sh[t] += x;
        __syncthreads();
    }
    int excl = sh[t] - v + prefix;
    if (i < NN) { g_rowptr[i] = excl; g_fillpos[i] = excl; }
    if (bid == 0 && t == 0) g_rowptr[NN] = NE;
}

// ---------------- CSR fill ---------------------------------------------------
__global__ void k_fill(const int* __restrict__ row, const int* __restrict__ col) {
    int e = blockIdx.x * blockDim.x + threadIdx.x;
    if (e < NE) {
        int p = atomicAdd(&g_fillpos[col[e]], 1);
        g_csrsrc[p] = row[e];
    }
}

// ---------------- layer-1 aggregation (gathers X/uY directly) + bf16 split ---
__global__ void k_agg1(const float* __restrict__ X, const float* __restrict__ uY) {
    int v = blockIdx.x;
    int j = threadIdx.x;
    float dv = g_dinv[v];
    float self = (j < 64) ? uY[v * 64 + j] : X[v * 128 + (j - 64)];
    float acc = dv * self;
    int beg = g_rowptr[v], end = g_rowptr[v + 1];
    for (int e = beg; e < end; e++) {
        int u = g_csrsrc[e];
        float du = g_dinv[u];
        float val = (j < 64) ? uY[u * 64 + j] : X[u * 128 + (j - 64)];
        acc += du * val;
    }
    float out = dv * acc;
    __nv_bfloat16 h = __float2bfloat16(out);
    g_Ah[(size_t)v * F1 + j] = h;
    g_Al[(size_t)v * F1 + j] = __float2bfloat16(out - __bfloat162float(h));
}

// ---------------- mma.sync GEMM, cp.async double-buffered --------------------
// D = Ah@Bh + Ah@Bl + Al@Bh (fp32 acc). CTA 128x128; 8 warps 4x2 (32x64 tiles).
// KC=16 chunks (32B rows, SW32); 2 buffers x (A 8KB + B 8KB) = 32KB static.
// Epilogue folds bias+ReLU+W2 -> g_z2 atomics; h1 never stored.
__global__ __launch_bounds__(256) void k_gemm(const float* __restrict__ b1,
                                              const float* __restrict__ W2) {
    __shared__ __nv_bfloat16 sAh[2][TM * KC];   // 4 KB per buffer
    __shared__ __nv_bfloat16 sAl[2][TM * KC];
    __shared__ __nv_bfloat16 sBh[2][TN * KC];
    __shared__ __nv_bfloat16 sBl[2][TN * KC];

    int tid = threadIdx.x;
    int wid = tid >> 5, lane = tid & 31;
    int wr = wid >> 1;          // 0..3  (32-row band)
    int wc = wid & 1;           // 0..1  (64-col band)
    int rowbase = blockIdx.y * TM;
    int colbase = blockIdx.x * TN;

    float acc[2][8][4];
    #pragma unroll
    for (int i = 0; i < 2; i++)
        #pragma unroll
        for (int j = 0; j < 8; j++)
            #pragma unroll
            for (int c = 0; c < 4; c++) acc[i][j][c] = 0.f;

    // loader mapping: thread -> (row m = tid>>1, 16B-half g = tid&1)
    int lm = tid >> 1, lg = tid & 1;
    int lr = rowbase + lm;
    int okA = (lr < NN) ? 16 : 0;
    uint32_t sdst = sw32((uint32_t)(lm * 32 + lg * 16));
    const char* srcAh = (const char*)&g_Ah[(size_t)lr * F1] + lg * 16;
    const char* srcAl = (const char*)&g_Al[(size_t)lr * F1] + lg * 16;
    const char* srcBh = (const char*)&g_Bh[(size_t)(colbase + lm) * F1] + lg * 16;
    const char* srcBl = (const char*)&g_Bl[(size_t)(colbase + lm) * F1] + lg * 16;

    // per-lane ldmatrix address components (32B rows)
    int a_row = wr * 32 + (lane & 15);                      // + mt*16
    int a_kb  = (lane & 16);
    int b_row = wc * 64 + (lane & 7) + ((lane & 16) >> 1);  // + p*16
    int b_kb  = (lane & 8) * 2;

    // preload chunk 0
    {
        uint32_t d0h = smem_u32(sAh[0]) + sdst, d0l = smem_u32(sAl[0]) + sdst;
        uint32_t e0h = smem_u32(sBh[0]) + sdst, e0l = smem_u32(sBl[0]) + sdst;
        cpa16(d0h, srcAh, okA);
        cpa16(d0l, srcAl, okA);
        cpa16(e0h, srcBh, 16);
        cpa16(e0l, srcBl, 16);
        cpa_commit();
    }

    #pragma unroll
    for (int c = 0; c < NCHUNK; c++) {
        int buf = c & 1;
        if (c < NCHUNK - 1) {
            int nb = buf ^ 1;
            int koff = (c + 1) * 32;   // bytes into the K dimension
            cpa16(smem_u32(sAh[nb]) + sdst, srcAh + koff, okA);
            cpa16(smem_u32(sAl[nb]) + sdst, srcAl + koff, okA);
            cpa16(smem_u32(sBh[nb]) + sdst, srcBh + koff, 16);
            cpa16(smem_u32(sBl[nb]) + sdst, srcBl + koff, 16);
            cpa_commit();
            cpa_wait1();
        } else {
            cpa_wait0();
        }
        __syncthreads();

        uint32_t bAh = smem_u32(sAh[buf]), bAl = smem_u32(sAl[buf]);
        uint32_t bBh = smem_u32(sBh[buf]), bBl = smem_u32(sBl[buf]);

        uint32_t af[2][4], bh[4][4], bl[4][4];
        #pragma unroll
        for (int p = 0; p < 4; p++) {
            uint32_t off = sw32((uint32_t)((b_row + p * 16) * 32 + b_kb));
            ldm_x4(bh[p], bBh + off);
            ldm_x4(bl[p], bBl + off);
        }
        #pragma unroll
        for (int mt = 0; mt < 2; mt++) {
            uint32_t off = sw32((uint32_t)((a_row + mt * 16) * 32 + a_kb));
            ldm_x4(af[mt], bAh + off);
        }
        // term 1: Ah @ Bh ; term 2: Ah @ Bl
        #pragma unroll
        for (int mt = 0; mt < 2; mt++)
            #pragma unroll
            for (int nt = 0; nt < 8; nt++) {
                mma16816(acc[mt][nt], af[mt], &bh[nt >> 1][(nt & 1) * 2]);
                mma16816(acc[mt][nt], af[mt], &bl[nt >> 1][(nt & 1) * 2]);
            }
        // A lo fragments (reuse registers)
        #pragma unroll
        for (int mt = 0; mt < 2; mt++) {
            uint32_t off = sw32((uint32_t)((a_row + mt * 16) * 32 + a_kb));
            ldm_x4(af[mt], bAl + off);
        }
        // term 3: Al @ Bh
        #pragma unroll
        for (int mt = 0; mt < 2; mt++)
            #pragma unroll
            for (int nt = 0; nt < 8; nt++)
                mma16816(acc[mt][nt], af[mt], &bh[nt >> 1][(nt & 1) * 2]);
        __syncthreads();
    }

    // ---- epilogue: bias + ReLU + W2 fold, straight from registers ----
    #pragma unroll
    for (int mt = 0; mt < 2; mt++) {
        #pragma unroll
        for (int rg = 0; rg < 2; rg++) {
            int r = rowbase + wr * 32 + mt * 16 + (lane >> 2) + rg * 8;
            float p0 = 0.f, p1 = 0.f;
            #pragma unroll
            for (int nt = 0; nt < 8; nt++) {
                #pragma unroll
                for (int q = 0; q < 2; q++) {
                    int col = colbase + wc * 64 + nt * 8 + (lane & 3) * 2 + q;
                    float v = fmaxf(acc[mt][nt][rg * 2 + q] + __ldg(&b1[col]), 0.f);
                    p0 += v * __ldg(&W2[col * 2 + 0]);
                    p1 += v * __ldg(&W2[col * 2 + 1]);
                }
            }
            p0 += __shfl_xor_sync(0xffffffffu, p0, 1);
            p1 += __shfl_xor_sync(0xffffffffu, p1, 1);
            p0 += __shfl_xor_sync(0xffffffffu, p0, 2);
            p1 += __shfl_xor_sync(0xffffffffu, p1, 2);
            if ((lane & 3) == 0 && r < NN) {
                atomicAdd(&g_z2[r * 2 + 0], p0);
                atomicAdd(&g_z2[r * 2 + 1], p1);
            }
        }
    }
}

// ---------------- layer-2 aggregation + bias + softmax -----------------------
__global__ void k_final(const float* __restrict__ b2, float* __restrict__ out) {
    int v = blockIdx.x * blockDim.x + threadIdx.x;
    if (v >= NN) return;
    float dv = g_dinv[v];
    float s0 = dv * g_z2[v * 2 + 0];
    float s1v = dv * g_z2[v * 2 + 1];
    int beg = g_rowptr[v], end = g_rowptr[v + 1];
    for (int e = beg; e < end; e++) {
        int u = g_csrsrc[e];
        float du = g_dinv[u];
        s0 += du * g_z2[u * 2 + 0];
        s1v += du * g_z2[u * 2 + 1];
    }
    float y0 = dv * s0 + b2[0];
    float y1 = dv * s1v + b2[1];
    float m = fmaxf(y0, y1);
    float e0 = __expf(y0 - m), e1 = __expf(y1 - m);
    float inv = 1.f / (e0 + e1);
    out[v * 2 + 0] = e0 * inv;
    out[v * 2 + 1] = e1 * inv;
}

// ---------------- launch ------------------------------------------------------
extern "C" void kernel_launch(void* const* d_in, const int* in_sizes, int n_in,
                              void* d_out, int out_size) {
    const int*   ei = (const int*)d_in[0];
    const float* X  = (const float*)d_in[1];
    const float* uY = (const float*)d_in[2];
    const float* W1 = (const float*)d_in[3];
    const float* b1 = (const float*)d_in[4];
    const float* W2 = (const float*)d_in[5];
    const float* b2 = (const float*)d_in[6];
    float* out = (float*)d_out;
    (void)in_sizes; (void)n_in; (void)out_size;

    const int* row = ei;        // edge_index[0] = sources
    const int* col = ei + NE;   // edge_index[1] = targets

    k_prolog<<<(PROLOG_N + 255) / 256, 256>>>(W1);
    k_degree<<<(NE + 255) / 256, 256>>>(col);
    k_scan1 <<<NBLK, SCAN_B>>>();
    k_scan3 <<<NBLK, SCAN_B>>>();
    k_fill  <<<(NE + 255) / 256, 256>>>(row, col);
    k_agg1  <<<NN, F1>>>(X, uY);
    k_gemm  <<<dim3(HID / TN, (NN + TM - 1) / TM), 256>>>(b1, W2);
    k_final <<<(NN + 255) / 256, 256>>>(b2, out);
}